// round 2
// baseline (speedup 1.0000x reference)
#include <cuda_runtime.h>
#include <math.h>

#define BSZ 32
#define CSZ 256
#define HH  56
#define WFQ 32
#define WWK 62
#define NPIX 3136
#define MSZ 16
#define KSZ 8
#define HIDN 16
#define PI_D 3.141592653589793238462643383279502884

__device__ float  g_ctx[BSZ * CSZ];
__device__ float  g_coeffs[BSZ * CSZ * MSZ * KSZ];
__device__ float  g_yspec[(size_t)BSZ * CSZ * NPIX];
__device__ float  g_yconv[(size_t)BSZ * CSZ * NPIX];
__device__ float  g_bnA[CSZ], g_bnB[CSZ];

__device__ float2 g_FwRT[HH * WFQ];   // [w0][v]
__device__ float2 g_Fh[HH * HH];      // [u][h]
__device__ float2 g_Gh[HH * HH];      // [h][u]
__device__ float2 g_GwT[WFQ * HH];    // [v][w0]

__device__ double g_Rf[WWK * HH];
__device__ double g_Rb[HH * WWK];
__device__ double g_tw62r[WWK], g_tw62i[WWK];

__device__ double rz_fwd(int j, int i) {           // 56 -> 62, ks = 1
    double s = (j + 0.5) * (56.0 / 62.0) - 0.5;
    double w = fmax(0.0, 1.0 - fabs(s - (double)i));
    double denom = 0.0;
    int i0 = (int)floor(s);
    for (int q = i0; q <= i0 + 1; ++q)
        if (q >= 0 && q < 56) denom += fmax(0.0, 1.0 - fabs(s - (double)q));
    return w / denom;
}
__device__ double rz_bwd(int j, int i) {           // 62 -> 56, antialias ks = 62/56
    double ks = 62.0 / 56.0;
    double s = (j + 0.5) * ks - 0.5;
    double w = fmax(0.0, 1.0 - fabs(s - (double)i) / ks);
    double denom = 0.0;
    int lo = (int)ceil(s - ks), hi = (int)floor(s + ks);
    if (lo < 0) lo = 0;
    if (hi > 61) hi = 61;
    for (int q = lo; q <= hi; ++q)
        denom += fmax(0.0, 1.0 - fabs(s - (double)q) / ks);
    return w / denom;
}

__global__ void k_init0() {
    int t = threadIdx.x;
    if (t < WWK) { double a = -2.0 * PI_D * t / 62.0; g_tw62r[t] = cos(a); g_tw62i[t] = sin(a); }
    for (int i = t; i < WWK * HH; i += blockDim.x) g_Rf[i] = rz_fwd(i / HH, i % HH);
    for (int i = t; i < HH * WWK; i += blockDim.x) g_Rb[i] = rz_bwd(i / WWK, i % WWK);
}

__global__ void k_init1() {
    const double SC = 1.0 / sqrt(56.0 * 62.0);
    int total = 1792 + 1792 + 3136 + 3136;
    for (int idx = blockIdx.x * blockDim.x + threadIdx.x; idx < total; idx += gridDim.x * blockDim.x) {
        if (idx < 1792) {                      // FwRT[w0][v]
            int w0 = idx / WFQ, v = idx % WFQ;
            double ar = 0, ai = 0;
            for (int w = 0; w < WWK; ++w) {
                double r = g_Rf[w * HH + w0]; int m = (v * w) % WWK;
                ar += g_tw62r[m] * r; ai += g_tw62i[m] * r;
            }
            g_FwRT[w0 * WFQ + v] = make_float2((float)(ar * SC), (float)(ai * SC));
        } else if (idx < 3584) {               // GwT[v][w0]
            int j = idx - 1792; int v = j / HH, w0 = j % HH;
            double cv = (v == 0 || v == 31) ? 1.0 : 2.0;
            double ar = 0, ai = 0;
            for (int w = 0; w < WWK; ++w) {
                double r = g_Rb[w0 * WWK + w]; int m = (v * w) % WWK;
                ar += g_tw62r[m] * r; ai -= g_tw62i[m] * r;
            }
            g_GwT[v * HH + w0] = make_float2((float)(ar * cv * SC), (float)(ai * cv * SC));
        } else if (idx < 6720) {               // Fh[u][h]
            int j = idx - 3584; int u = j / HH, h = j % HH;
            double a = -2.0 * PI_D * ((u * h) % HH) / 56.0;
            g_Fh[u * HH + h] = make_float2((float)cos(a), (float)sin(a));
        } else {                               // Gh[h][u]
            int j = idx - 6720; int h = j / HH, u = j % HH;
            double a = 2.0 * PI_D * ((u * h) % HH) / 56.0;
            g_Gh[h * HH + u] = make_float2((float)cos(a), (float)sin(a));
        }
    }
}

__global__ void k_ctx(const float* __restrict__ x) {
    int plane = blockIdx.x;
    const float4* p = (const float4*)(x + (size_t)plane * NPIX);
    float s = 0.f;
    for (int i = threadIdx.x; i < NPIX / 4; i += blockDim.x) {
        float4 v = p[i]; s += v.x + v.y + v.z + v.w;
    }
    for (int o = 16; o > 0; o >>= 1) s += __shfl_xor_sync(0xffffffffu, s, o);
    __shared__ float red[4];
    int warp = threadIdx.x >> 5, lane = threadIdx.x & 31;
    if (lane == 0) red[warp] = s;
    __syncthreads();
    if (threadIdx.x == 0)
        g_ctx[plane] = (red[0] + red[1] + red[2] + red[3]) * (1.0f / NPIX);
}

__global__ void __launch_bounds__(256) k_head(
    const float* __restrict__ fc1_w, const float* __restrict__ fc1_b,
    const float* __restrict__ ln_g,  const float* __restrict__ ln_b,
    const float* __restrict__ fh_w,  const float* __restrict__ fh_b)
{
    int b = blockIdx.x, t = threadIdx.x;
    int warp = t >> 5, lane = t & 31;
    __shared__ float sctx[CSZ];
    __shared__ float shid[HIDN];
    __shared__ float sstat[2];
    sctx[t] = g_ctx[b * CSZ + t];
    __syncthreads();
    for (int rep = 0; rep < 2; ++rep) {
        int hidx = warp * 2 + rep;
        float acc = 0.f;
        for (int c = lane; c < CSZ; c += 32) acc += sctx[c] * fc1_w[hidx * CSZ + c];
        for (int o = 16; o > 0; o >>= 1) acc += __shfl_xor_sync(0xffffffffu, acc, o);
        if (lane == 0) shid[hidx] = acc + fc1_b[hidx];
    }
    __syncthreads();
    if (t == 0) {
        float mu = 0.f;
        for (int i = 0; i < HIDN; ++i) mu += shid[i];
        mu *= (1.0f / HIDN);
        float var = 0.f;
        for (int i = 0; i < HIDN; ++i) { float d = shid[i] - mu; var += d * d; }
        sstat[0] = mu; sstat[1] = rsqrtf(var * (1.0f / HIDN) + 1e-5f);
    }
    __syncthreads();
    float hact[HIDN];
#pragma unroll
    for (int i = 0; i < HIDN; ++i)
        hact[i] = fmaxf((shid[i] - sstat[0]) * sstat[1] * ln_g[i] + ln_b[i], 0.f);
    for (int r = 0; r < 16; ++r) {
        int row0 = (t + 256 * r) * KSZ;
        float lg[KSZ]; float mx = -1e30f;
#pragma unroll
        for (int k = 0; k < KSZ; ++k) {
            const float* wr = fh_w + (size_t)(row0 + k) * HIDN;
            float a = fh_b[row0 + k];
#pragma unroll
            for (int i = 0; i < HIDN; ++i) a += hact[i] * wr[i];
            lg[k] = a; mx = fmaxf(mx, a);
        }
        float sum = 0.f;
#pragma unroll
        for (int k = 0; k < KSZ; ++k) { lg[k] = expf(lg[k] - mx); sum += lg[k]; }
        float inv = 1.0f / sum;
#pragma unroll
        for (int k = 0; k < KSZ; ++k)
            g_coeffs[(size_t)b * (CSZ * MSZ * KSZ) + row0 + k] = lg[k] * inv;
    }
}

// per-plane fused resize/DFT/mask/iDFT/resize
__global__ void __launch_bounds__(256) k_spec(
    const float* __restrict__ x,
    const float* __restrict__ br, const float* __restrict__ bi)
{
    __shared__ __align__(16) float sm[10432];
    float2* B1 = (float2*)sm;                  // 1792 f2
    float2* B2 = (float2*)(sm + 3584);         // 1792 f2
    float*  BX = sm + 7168;                    // 3136 f (aliased by B3)
    float2* B3 = (float2*)(sm + 7168);
    float*  sCo = sm + 10304;                  // 128 f

    int plane = blockIdx.x;
    int t = threadIdx.x, warp = t >> 5, lane = t & 31;
    const float* xp = x + (size_t)plane * NPIX;

    for (int i = t; i < NPIX; i += 256) BX[i] = xp[i];
    if (t < 128) sCo[t] = g_coeffs[(size_t)plane * 128 + t];
    for (int i = t; i < 1792; i += 256) B1[i] = g_FwRT[i];
    __syncthreads();

    // T1[h][v] = sum_w x[h][w] * FwRT[w][v]
    {
        float2 acc[7];
#pragma unroll
        for (int r = 0; r < 7; ++r) acc[r] = make_float2(0.f, 0.f);
        int h0 = warp * 7;
        for (int w = 0; w < HH; w += 2) {
            float2 f0 = B1[w * WFQ + lane];
            float2 f1 = B1[(w + 1) * WFQ + lane];
#pragma unroll
            for (int r = 0; r < 7; ++r) {
                float2 a = *(const float2*)&BX[(h0 + r) * HH + w];
                acc[r].x += a.x * f0.x + a.y * f1.x;
                acc[r].y += a.x * f0.y + a.y * f1.y;
            }
        }
#pragma unroll
        for (int r = 0; r < 7; ++r) B2[(h0 + r) * WFQ + lane] = acc[r];
    }
    __syncthreads();

    // X = Fh @ T1, then mask -> Y in B1 (Fh streamed in halves)
    for (int half = 0; half < 2; ++half) {
        int ub = half * 28;
        for (int i = t; i < 28 * HH; i += 256) B3[i] = g_Fh[ub * HH + i];
        __syncthreads();
        float2 acc[4];
#pragma unroll
        for (int r = 0; r < 4; ++r) acc[r] = make_float2(0.f, 0.f);
        for (int h = 0; h < HH; ++h) {
            float2 tt = B2[h * WFQ + lane];
#pragma unroll
            for (int rr = 0; rr < 4; ++rr) {
                int ul = warp + 8 * rr;
                if (ul < 28) {
                    float2 fh = B3[ul * HH + h];
                    acc[rr].x += fh.x * tt.x - fh.y * tt.y;
                    acc[rr].y += fh.x * tt.y + fh.y * tt.x;
                }
            }
        }
#pragma unroll
        for (int rr = 0; rr < 4; ++rr) {
            int ul = warp + 8 * rr;
            if (ul < 28) {
                int u = ub + ul;
                const float* co = sCo + ((u / 14) * 4 + (lane >> 3)) * KSZ;
                float mr = 0.f, mi = 0.f;
#pragma unroll
                for (int k = 0; k < KSZ; ++k) {
                    int bidx = k * (HH * WFQ) + u * WFQ + lane;
                    mr += co[k] * br[bidx];
                    mi += co[k] * bi[bidx];
                }
                float2 X = acc[rr];
                B1[u * WFQ + lane] = make_float2(X.x * mr - X.y * mi, X.x * mi + X.y * mr);
            }
        }
        __syncthreads();
    }

    // T2 = Gh @ Y -> B2 (Gh streamed)
    for (int half = 0; half < 2; ++half) {
        int hb = half * 28;
        for (int i = t; i < 28 * HH; i += 256) B3[i] = g_Gh[hb * HH + i];
        __syncthreads();
        float2 acc[4];
#pragma unroll
        for (int r = 0; r < 4; ++r) acc[r] = make_float2(0.f, 0.f);
        for (int u = 0; u < HH; ++u) {
            float2 yy = B1[u * WFQ + lane];
#pragma unroll
            for (int rr = 0; rr < 4; ++rr) {
                int hl = warp + 8 * rr;
                if (hl < 28) {
                    float2 gh = B3[hl * HH + u];
                    acc[rr].x += gh.x * yy.x - gh.y * yy.y;
                    acc[rr].y += gh.x * yy.y + gh.y * yy.x;
                }
            }
        }
#pragma unroll
        for (int rr = 0; rr < 4; ++rr) {
            int hl = warp + 8 * rr;
            if (hl < 28) B2[(hb + hl) * WFQ + lane] = acc[rr];
        }
        __syncthreads();
    }

    // y[h][w0] = Re( T2[h][:] . GwT[:][w0] )
    for (int i = t; i < 1792; i += 256) B1[i] = g_GwT[i];
    __syncthreads();
    float* outp = g_yspec + (size_t)plane * NPIX;
    for (int grp = 0; grp < 2; ++grp) {
        int nr = grp ? 3 : 4;
        float a1[4] = {0.f, 0.f, 0.f, 0.f};
        float a2[4] = {0.f, 0.f, 0.f, 0.f};
        for (int v = 0; v < WFQ; ++v) {
            float2 g1 = B1[v * HH + lane];
            float2 g2 = (lane < 24) ? B1[v * HH + 32 + lane] : make_float2(0.f, 0.f);
#pragma unroll
            for (int r = 0; r < 4; ++r) {
                if (r < nr) {
                    float2 tt = B2[(warp + 8 * (grp * 4 + r)) * WFQ + v];
                    a1[r] += tt.x * g1.x - tt.y * g1.y;
                    a2[r] += tt.x * g2.x - tt.y * g2.y;
                }
            }
        }
#pragma unroll
        for (int r = 0; r < 4; ++r) {
            if (r < nr) {
                int h = warp + 8 * (grp * 4 + r);
                outp[h * HH + lane] = a1[r];
                if (lane < 24) outp[h * HH + 32 + lane] = a2[r];
            }
        }
    }
}

// 1x1 conv: out[b][o][p] = sum_c W[o][c] * yspec[b][c][p]
__global__ void __launch_bounds__(256) k_conv(const float* __restrict__ W) {
    __shared__ float As[16][64];
    __shared__ float Bs[16][68];
    int b = blockIdx.z, mo = blockIdx.y * 64, no = blockIdx.x * 64;
    const float* Y = g_yspec + (size_t)b * CSZ * NPIX;
    float* Out = g_yconv + (size_t)b * CSZ * NPIX;
    int t = threadIdx.x;
    int tx = t & 15, ty = t >> 4;
    float acc[4][4] = {};
    for (int kk = 0; kk < CSZ; kk += 16) {
        int r = t & 63, cq = t >> 6;
        float4 wv = *(const float4*)&W[(size_t)(mo + r) * CSZ + kk + cq * 4];
        As[cq * 4 + 0][r] = wv.x; As[cq * 4 + 1][r] = wv.y;
        As[cq * 4 + 2][r] = wv.z; As[cq * 4 + 3][r] = wv.w;
        float4 yv = *(const float4*)&Y[(size_t)(kk + (t >> 4)) * NPIX + no + (t & 15) * 4];
        *(float4*)&Bs[t >> 4][(t & 15) * 4] = yv;
        __syncthreads();
#pragma unroll
        for (int k = 0; k < 16; ++k) {
            float a[4], bb[4];
#pragma unroll
            for (int i = 0; i < 4; ++i) a[i] = As[k][ty * 4 + i];
#pragma unroll
            for (int j = 0; j < 4; ++j) bb[j] = Bs[k][tx * 4 + j];
#pragma unroll
            for (int i = 0; i < 4; ++i)
#pragma unroll
                for (int j = 0; j < 4; ++j) acc[i][j] += a[i] * bb[j];
        }
        __syncthreads();
    }
#pragma unroll
    for (int i = 0; i < 4; ++i) {
        float4 v = make_float4(acc[i][0], acc[i][1], acc[i][2], acc[i][3]);
        *(float4*)&Out[(size_t)(mo + ty * 4 + i) * NPIX + no + tx * 4] = v;
    }
}

__global__ void k_bnstat(const float* __restrict__ bn_g, const float* __restrict__ bn_b) {
    int o = blockIdx.x, t = threadIdx.x;
    float s1 = 0.f, s2 = 0.f;
    for (int b = 0; b < BSZ; ++b) {
        const float* p = g_yconv + (size_t)b * CSZ * NPIX + (size_t)o * NPIX;
        for (int i = t; i < NPIX; i += 256) { float v = p[i]; s1 += v; s2 += v * v; }
    }
    __shared__ double r1[256], r2[256];
    r1[t] = s1; r2[t] = s2; __syncthreads();
    for (int st = 128; st > 0; st >>= 1) {
        if (t < st) { r1[t] += r1[t + st]; r2[t] += r2[t + st]; }
        __syncthreads();
    }
    if (t == 0) {
        double N = (double)BSZ * NPIX;
        double mean = r1[0] / N, var = r2[0] / N - (r1[0] / N) * (r1[0] / N);
        float inv = (float)(1.0 / sqrt(var + 1e-5));
        float A = bn_g[o] * inv;
        g_bnA[o] = A;
        g_bnB[o] = bn_b[o] - (float)mean * A;
    }
}

__global__ void k_bnapply(float* __restrict__ out) {
    int i4 = blockIdx.x * blockDim.x + threadIdx.x;     // float4 index
    int c = (i4 / (NPIX / 4)) % CSZ;
    float A = g_bnA[c], Bv = g_bnB[c];
    float4 v = ((const float4*)g_yconv)[i4];
    v.x = v.x * A + Bv; v.y = v.y * A + Bv; v.z = v.z * A + Bv; v.w = v.w * A + Bv;
    ((float4*)out)[i4] = v;
}

extern "C" void kernel_launch(void* const* d_in, const int* in_sizes, int n_in,
                              void* d_out, int out_size) {
    const float* x      = (const float*)d_in[0];
    const float* fc1_w  = (const float*)d_in[1];
    const float* fc1_b  = (const float*)d_in[2];
    const float* ln_g   = (const float*)d_in[3];
    const float* ln_b   = (const float*)d_in[4];
    const float* fh_w   = (const float*)d_in[5];
    const float* fh_b   = (const float*)d_in[6];
    const float* br     = (const float*)d_in[7];
    const float* bi     = (const float*)d_in[8];
    const float* conv_w = (const float*)d_in[9];
    const float* bn_g   = (const float*)d_in[10];
    const float* bn_b   = (const float*)d_in[11];
    (void)in_sizes; (void)n_in; (void)out_size;

    k_init0<<<1, 256>>>();
    k_init1<<<40, 256>>>();
    k_ctx<<<BSZ * CSZ, 128>>>(x);
    k_head<<<BSZ, 256>>>(fc1_w, fc1_b, ln_g, ln_b, fh_w, fh_b);
    k_spec<<<BSZ * CSZ, 256>>>(x, br, bi);
    dim3 gc(49, 4, BSZ);
    k_conv<<<gc, 256>>>(conv_w);
    k_bnstat<<<CSZ, 256>>>(bn_g, bn_b);
    k_bnapply<<<(BSZ * CSZ * NPIX) / 1024, 256>>>((float*)d_out);
}

// round 3
// speedup vs baseline: 1.2721x; 1.2721x over previous
#include <cuda_runtime.h>
#include <math.h>

#define BSZ 32
#define CSZ 256
#define HH  56
#define WFQ 32
#define WWK 62
#define NPIX 3136
#define MSZ 16
#define KSZ 8
#define HIDN 16
#define PI_D 3.141592653589793238462643383279502884

__device__ float  g_ctx[BSZ * CSZ];
__device__ float  g_hact[BSZ * HIDN];
__device__ float  g_coeffs[BSZ * CSZ * MSZ * KSZ];
__device__ float  g_yspec[(size_t)BSZ * CSZ * NPIX];
__device__ float  g_yconv[(size_t)BSZ * CSZ * NPIX];
__device__ float  g_bnA[CSZ], g_bnB[CSZ];

__device__ float2 g_FwRT[HH * WFQ];   // [w0][v]
__device__ float2 g_Fh[HH * HH];      // [u][h]
__device__ float2 g_Gh[HH * HH];      // [h][u]
__device__ float2 g_GwT[WFQ * HH];    // [v][w0]

__device__ double g_Rf[WWK * HH];
__device__ double g_Rb[HH * WWK];
__device__ double g_tw62r[WWK], g_tw62i[WWK];

__device__ double rz_fwd(int j, int i) {           // 56 -> 62, ks = 1
    double s = (j + 0.5) * (56.0 / 62.0) - 0.5;
    double w = fmax(0.0, 1.0 - fabs(s - (double)i));
    double denom = 0.0;
    int i0 = (int)floor(s);
    for (int q = i0; q <= i0 + 1; ++q)
        if (q >= 0 && q < 56) denom += fmax(0.0, 1.0 - fabs(s - (double)q));
    return w / denom;
}
__device__ double rz_bwd(int j, int i) {           // 62 -> 56, antialias ks = 62/56
    double ks = 62.0 / 56.0;
    double s = (j + 0.5) * ks - 0.5;
    double w = fmax(0.0, 1.0 - fabs(s - (double)i) / ks);
    double denom = 0.0;
    int lo = (int)ceil(s - ks), hi = (int)floor(s + ks);
    if (lo < 0) lo = 0;
    if (hi > 61) hi = 61;
    for (int q = lo; q <= hi; ++q)
        denom += fmax(0.0, 1.0 - fabs(s - (double)q) / ks);
    return w / denom;
}

__global__ void k_init0() {
    int t = threadIdx.x;
    if (t < WWK) { double a = -2.0 * PI_D * t / 62.0; g_tw62r[t] = cos(a); g_tw62i[t] = sin(a); }
    for (int i = t; i < WWK * HH; i += blockDim.x) g_Rf[i] = rz_fwd(i / HH, i % HH);
    for (int i = t; i < HH * WWK; i += blockDim.x) g_Rb[i] = rz_bwd(i / WWK, i % WWK);
}

__global__ void k_init1() {
    const double SC = 1.0 / sqrt(56.0 * 62.0);
    int total = 1792 + 1792 + 3136 + 3136;
    for (int idx = blockIdx.x * blockDim.x + threadIdx.x; idx < total; idx += gridDim.x * blockDim.x) {
        if (idx < 1792) {                      // FwRT[w0][v]
            int w0 = idx / WFQ, v = idx % WFQ;
            double ar = 0, ai = 0;
            for (int w = 0; w < WWK; ++w) {
                double r = g_Rf[w * HH + w0]; int m = (v * w) % WWK;
                ar += g_tw62r[m] * r; ai += g_tw62i[m] * r;
            }
            g_FwRT[w0 * WFQ + v] = make_float2((float)(ar * SC), (float)(ai * SC));
        } else if (idx < 3584) {               // GwT[v][w0]
            int j = idx - 1792; int v = j / HH, w0 = j % HH;
            double cv = (v == 0 || v == 31) ? 1.0 : 2.0;
            double ar = 0, ai = 0;
            for (int w = 0; w < WWK; ++w) {
                double r = g_Rb[w0 * WWK + w]; int m = (v * w) % WWK;
                ar += g_tw62r[m] * r; ai -= g_tw62i[m] * r;
            }
            g_GwT[v * HH + w0] = make_float2((float)(ar * cv * SC), (float)(ai * cv * SC));
        } else if (idx < 6720) {               // Fh[u][h]
            int j = idx - 3584; int u = j / HH, h = j % HH;
            double a = -2.0 * PI_D * ((u * h) % HH) / 56.0;
            g_Fh[u * HH + h] = make_float2((float)cos(a), (float)sin(a));
        } else {                               // Gh[h][u]
            int j = idx - 6720; int h = j / HH, u = j % HH;
            double a = 2.0 * PI_D * ((u * h) % HH) / 56.0;
            g_Gh[h * HH + u] = make_float2((float)cos(a), (float)(sin(a)));
        }
    }
}

__global__ void k_ctx(const float* __restrict__ x) {
    int plane = blockIdx.x;
    const float4* p = (const float4*)(x + (size_t)plane * NPIX);
    float s = 0.f;
    for (int i = threadIdx.x; i < NPIX / 4; i += blockDim.x) {
        float4 v = p[i]; s += v.x + v.y + v.z + v.w;
    }
    for (int o = 16; o > 0; o >>= 1) s += __shfl_xor_sync(0xffffffffu, s, o);
    __shared__ float red[4];
    int warp = threadIdx.x >> 5, lane = threadIdx.x & 31;
    if (lane == 0) red[warp] = s;
    __syncthreads();
    if (threadIdx.x == 0)
        g_ctx[plane] = (red[0] + red[1] + red[2] + red[3]) * (1.0f / NPIX);
}

// fc1 -> LN -> ReLU, one block per batch -> g_hact
__global__ void __launch_bounds__(256) k_head1(
    const float* __restrict__ fc1_w, const float* __restrict__ fc1_b,
    const float* __restrict__ ln_g,  const float* __restrict__ ln_b)
{
    int b = blockIdx.x, t = threadIdx.x;
    int warp = t >> 5, lane = t & 31;
    __shared__ float sctx[CSZ];
    __shared__ float shid[HIDN];
    __shared__ float sstat[2];
    sctx[t] = g_ctx[b * CSZ + t];
    __syncthreads();
    for (int rep = 0; rep < 2; ++rep) {
        int hidx = warp * 2 + rep;
        float acc = 0.f;
        for (int c = lane; c < CSZ; c += 32) acc += sctx[c] * fc1_w[hidx * CSZ + c];
        for (int o = 16; o > 0; o >>= 1) acc += __shfl_xor_sync(0xffffffffu, acc, o);
        if (lane == 0) shid[hidx] = acc + fc1_b[hidx];
    }
    __syncthreads();
    if (t == 0) {
        float mu = 0.f;
        for (int i = 0; i < HIDN; ++i) mu += shid[i];
        mu *= (1.0f / HIDN);
        float var = 0.f;
        for (int i = 0; i < HIDN; ++i) { float d = shid[i] - mu; var += d * d; }
        sstat[0] = mu; sstat[1] = rsqrtf(var * (1.0f / HIDN) + 1e-5f);
    }
    __syncthreads();
    if (t < HIDN)
        g_hact[b * HIDN + t] =
            fmaxf((shid[t] - sstat[0]) * sstat[1] * ln_g[t] + ln_b[t], 0.f);
}

// fourier head + softmax. warp -> one (c,m) group, lane -> batch.
// All lanes read the same fh_w addresses (L1 broadcast); fh_w streamed once.
__global__ void __launch_bounds__(256) k_head2(
    const float* __restrict__ fh_w, const float* __restrict__ fh_b)
{
    __shared__ float sH[BSZ * 17];
    int t = threadIdx.x;
    for (int i = t; i < BSZ * HIDN; i += 256)
        sH[(i >> 4) * 17 + (i & 15)] = g_hact[i];
    __syncthreads();
    int b = t & 31;
    int grp = blockIdx.x * 8 + (t >> 5);          // 512 blocks * 8 warps = 4096 groups
    float h[HIDN];
#pragma unroll
    for (int i = 0; i < HIDN; ++i) h[i] = sH[b * 17 + i];

    const float4* wp = (const float4*)(fh_w + (size_t)grp * KSZ * HIDN);
    float lg[KSZ]; float mx = -1e30f;
#pragma unroll
    for (int k = 0; k < KSZ; ++k) {
        float4 w0 = wp[k * 4 + 0], w1 = wp[k * 4 + 1], w2 = wp[k * 4 + 2], w3 = wp[k * 4 + 3];
        float a = fh_b[grp * KSZ + k];
        a += h[0]*w0.x + h[1]*w0.y + h[2]*w0.z + h[3]*w0.w;
        a += h[4]*w1.x + h[5]*w1.y + h[6]*w1.z + h[7]*w1.w;
        a += h[8]*w2.x + h[9]*w2.y + h[10]*w2.z + h[11]*w2.w;
        a += h[12]*w3.x + h[13]*w3.y + h[14]*w3.z + h[15]*w3.w;
        lg[k] = a; mx = fmaxf(mx, a);
    }
    float sum = 0.f;
#pragma unroll
    for (int k = 0; k < KSZ; ++k) { lg[k] = expf(lg[k] - mx); sum += lg[k]; }
    float inv = 1.0f / sum;
    float* out = g_coeffs + (size_t)b * (CSZ * MSZ * KSZ) + grp * KSZ;
    float4 o0 = make_float4(lg[0]*inv, lg[1]*inv, lg[2]*inv, lg[3]*inv);
    float4 o1 = make_float4(lg[4]*inv, lg[5]*inv, lg[6]*inv, lg[7]*inv);
    ((float4*)out)[0] = o0;
    ((float4*)out)[1] = o1;
}

// per-plane fused resize/DFT/mask/iDFT/resize
__global__ void __launch_bounds__(256) k_spec(
    const float* __restrict__ x,
    const float* __restrict__ br, const float* __restrict__ bi)
{
    __shared__ __align__(16) float sm[10432];
    float2* B1 = (float2*)sm;                  // 1792 f2
    float2* B2 = (float2*)(sm + 3584);         // 1792 f2
    float*  BX = sm + 7168;                    // 3136 f (aliased by B3)
    float2* B3 = (float2*)(sm + 7168);
    float*  sCo = sm + 10304;                  // 128 f

    int plane = blockIdx.x;
    int t = threadIdx.x, warp = t >> 5, lane = t & 31;
    const float* xp = x + (size_t)plane * NPIX;

    for (int i = t; i < NPIX; i += 256) BX[i] = xp[i];
    if (t < 128) sCo[t] = g_coeffs[(size_t)plane * 128 + t];
    for (int i = t; i < 1792; i += 256) B1[i] = g_FwRT[i];
    __syncthreads();

    // T1[h][v] = sum_w x[h][w] * FwRT[w][v]
    {
        float2 acc[7];
#pragma unroll
        for (int r = 0; r < 7; ++r) acc[r] = make_float2(0.f, 0.f);
        int h0 = warp * 7;
        for (int w = 0; w < HH; w += 2) {
            float2 f0 = B1[w * WFQ + lane];
            float2 f1 = B1[(w + 1) * WFQ + lane];
#pragma unroll
            for (int r = 0; r < 7; ++r) {
                float2 a = *(const float2*)&BX[(h0 + r) * HH + w];
                acc[r].x += a.x * f0.x + a.y * f1.x;
                acc[r].y += a.x * f0.y + a.y * f1.y;
            }
        }
#pragma unroll
        for (int r = 0; r < 7; ++r) B2[(h0 + r) * WFQ + lane] = acc[r];
    }
    __syncthreads();

    // X = Fh @ T1, then mask -> Y in B1 (Fh streamed in halves)
    for (int half = 0; half < 2; ++half) {
        int ub = half * 28;
        for (int i = t; i < 28 * HH; i += 256) B3[i] = g_Fh[ub * HH + i];
        __syncthreads();
        float2 acc[4];
#pragma unroll
        for (int r = 0; r < 4; ++r) acc[r] = make_float2(0.f, 0.f);
        for (int h = 0; h < HH; ++h) {
            float2 tt = B2[h * WFQ + lane];
#pragma unroll
            for (int rr = 0; rr < 4; ++rr) {
                int ul = warp + 8 * rr;
                if (ul < 28) {
                    float2 fh = B3[ul * HH + h];
                    acc[rr].x += fh.x * tt.x - fh.y * tt.y;
                    acc[rr].y += fh.x * tt.y + fh.y * tt.x;
                }
            }
        }
#pragma unroll
        for (int rr = 0; rr < 4; ++rr) {
            int ul = warp + 8 * rr;
            if (ul < 28) {
                int u = ub + ul;
                const float* co = sCo + ((u / 14) * 4 + (lane >> 3)) * KSZ;
                float mr = 0.f, mi = 0.f;
#pragma unroll
                for (int k = 0; k < KSZ; ++k) {
                    int bidx = k * (HH * WFQ) + u * WFQ + lane;
                    mr += co[k] * br[bidx];
                    mi += co[k] * bi[bidx];
                }
                float2 X = acc[rr];
                B1[u * WFQ + lane] = make_float2(X.x * mr - X.y * mi, X.x * mi + X.y * mr);
            }
        }
        __syncthreads();
    }

    // T2 = Gh @ Y -> B2 (Gh streamed)
    for (int half = 0; half < 2; ++half) {
        int hb = half * 28;
        for (int i = t; i < 28 * HH; i += 256) B3[i] = g_Gh[hb * HH + i];
        __syncthreads();
        float2 acc[4];
#pragma unroll
        for (int r = 0; r < 4; ++r) acc[r] = make_float2(0.f, 0.f);
        for (int u = 0; u < HH; ++u) {
            float2 yy = B1[u * WFQ + lane];
#pragma unroll
            for (int rr = 0; rr < 4; ++rr) {
                int hl = warp + 8 * rr;
                if (hl < 28) {
                    float2 gh = B3[hl * HH + u];
                    acc[rr].x += gh.x * yy.x - gh.y * yy.y;
                    acc[rr].y += gh.x * yy.y + gh.y * yy.x;
                }
            }
        }
#pragma unroll
        for (int rr = 0; rr < 4; ++rr) {
            int hl = warp + 8 * rr;
            if (hl < 28) B2[(hb + hl) * WFQ + lane] = acc[rr];
        }
        __syncthreads();
    }

    // y[h][w0] = Re( T2[h][:] . GwT[:][w0] )
    for (int i = t; i < 1792; i += 256) B1[i] = g_GwT[i];
    __syncthreads();
    float* outp = g_yspec + (size_t)plane * NPIX;
    for (int grp = 0; grp < 2; ++grp) {
        int nr = grp ? 3 : 4;
        float a1[4] = {0.f, 0.f, 0.f, 0.f};
        float a2[4] = {0.f, 0.f, 0.f, 0.f};
        for (int v = 0; v < WFQ; ++v) {
            float2 g1 = B1[v * HH + lane];
            float2 g2 = (lane < 24) ? B1[v * HH + 32 + lane] : make_float2(0.f, 0.f);
#pragma unroll
            for (int r = 0; r < 4; ++r) {
                if (r < nr) {
                    float2 tt = B2[(warp + 8 * (grp * 4 + r)) * WFQ + v];
                    a1[r] += tt.x * g1.x - tt.y * g1.y;
                    a2[r] += tt.x * g2.x - tt.y * g2.y;
                }
            }
        }
#pragma unroll
        for (int r = 0; r < 4; ++r) {
            if (r < nr) {
                int h = warp + 8 * (grp * 4 + r);
                outp[h * HH + lane] = a1[r];
                if (lane < 24) outp[h * HH + 32 + lane] = a2[r];
            }
        }
    }
}

// 1x1 conv: out[b][o][p] = sum_c W[o][c] * yspec[b][c][p], 128x64 tile, 8x4/thread
__global__ void __launch_bounds__(256) k_conv(const float* __restrict__ W) {
    __shared__ float As[16][128];
    __shared__ float Bs[16][68];
    int b = blockIdx.z, mo = blockIdx.y * 128, no = blockIdx.x * 64;
    const float* Y = g_yspec + (size_t)b * CSZ * NPIX;
    float* Out = g_yconv + (size_t)b * CSZ * NPIX;
    int t = threadIdx.x;
    int tx = t & 15, ty = t >> 4;
    float acc[8][4] = {};
    for (int kk = 0; kk < CSZ; kk += 16) {
#pragma unroll
        for (int it = 0; it < 2; ++it) {
            int r = (t >> 2) + 64 * it, q = t & 3;
            float4 wv = *(const float4*)&W[(size_t)(mo + r) * CSZ + kk + q * 4];
            As[q * 4 + 0][r] = wv.x; As[q * 4 + 1][r] = wv.y;
            As[q * 4 + 2][r] = wv.z; As[q * 4 + 3][r] = wv.w;
        }
        float4 yv = *(const float4*)&Y[(size_t)(kk + (t >> 4)) * NPIX + no + (t & 15) * 4];
        *(float4*)&Bs[t >> 4][(t & 15) * 4] = yv;
        __syncthreads();
#pragma unroll
        for (int k = 0; k < 16; ++k) {
            float a[8], bb[4];
            *(float4*)&a[0] = *(float4*)&As[k][ty * 8];
            *(float4*)&a[4] = *(float4*)&As[k][ty * 8 + 4];
            *(float4*)&bb[0] = *(float4*)&Bs[k][tx * 4];
#pragma unroll
            for (int i = 0; i < 8; ++i)
#pragma unroll
                for (int j = 0; j < 4; ++j) acc[i][j] += a[i] * bb[j];
        }
        __syncthreads();
    }
#pragma unroll
    for (int i = 0; i < 8; ++i) {
        float4 v = make_float4(acc[i][0], acc[i][1], acc[i][2], acc[i][3]);
        *(float4*)&Out[(size_t)(mo + ty * 8 + i) * NPIX + no + tx * 4] = v;
    }
}

__global__ void k_bnstat(const float* __restrict__ bn_g, const float* __restrict__ bn_b) {
    int o = blockIdx.x, t = threadIdx.x;
    float s1 = 0.f, s2 = 0.f;
    for (int b = 0; b < BSZ; ++b) {
        const float* p = g_yconv + (size_t)b * CSZ * NPIX + (size_t)o * NPIX;
        for (int i = t; i < NPIX; i += 256) { float v = p[i]; s1 += v; s2 += v * v; }
    }
    __shared__ double r1[256], r2[256];
    r1[t] = s1; r2[t] = s2; __syncthreads();
    for (int st = 128; st > 0; st >>= 1) {
        if (t < st) { r1[t] += r1[t + st]; r2[t] += r2[t + st]; }
        __syncthreads();
    }
    if (t == 0) {
        double N = (double)BSZ * NPIX;
        double mean = r1[0] / N, var = r2[0] / N - (r1[0] / N) * (r1[0] / N);
        float inv = (float)(1.0 / sqrt(var + 1e-5));
        float A = bn_g[o] * inv;
        g_bnA[o] = A;
        g_bnB[o] = bn_b[o] - (float)mean * A;
    }
}

__global__ void k_bnapply(float* __restrict__ out) {
    int i4 = blockIdx.x * blockDim.x + threadIdx.x;
    int c = (i4 / (NPIX / 4)) % CSZ;
    float A = g_bnA[c], Bv = g_bnB[c];
    float4 v = ((const float4*)g_yconv)[i4];
    v.x = v.x * A + Bv; v.y = v.y * A + Bv; v.z = v.z * A + Bv; v.w = v.w * A + Bv;
    ((float4*)out)[i4] = v;
}

extern "C" void kernel_launch(void* const* d_in, const int* in_sizes, int n_in,
                              void* d_out, int out_size) {
    const float* x      = (const float*)d_in[0];
    const float* fc1_w  = (const float*)d_in[1];
    const float* fc1_b  = (const float*)d_in[2];
    const float* ln_g   = (const float*)d_in[3];
    const float* ln_b   = (const float*)d_in[4];
    const float* fh_w   = (const float*)d_in[5];
    const float* fh_b   = (const float*)d_in[6];
    const float* br     = (const float*)d_in[7];
    const float* bi     = (const float*)d_in[8];
    const float* conv_w = (const float*)d_in[9];
    const float* bn_g   = (const float*)d_in[10];
    const float* bn_b   = (const float*)d_in[11];
    (void)in_sizes; (void)n_in; (void)out_size;

    k_init0<<<1, 256>>>();
    k_init1<<<40, 256>>>();
    k_ctx<<<BSZ * CSZ, 128>>>(x);
    k_head1<<<BSZ, 256>>>(fc1_w, fc1_b, ln_g, ln_b);
    k_head2<<<512, 256>>>(fh_w, fh_b);
    k_spec<<<BSZ * CSZ, 256>>>(x, br, bi);
    dim3 gc(49, 2, BSZ);
    k_conv<<<gc, 256>>>(conv_w);
    k_bnstat<<<CSZ, 256>>>(bn_g, bn_b);
    k_bnapply<<<(BSZ * CSZ * NPIX) / 1024, 256>>>((float*)d_out);
}

// round 4
// speedup vs baseline: 1.2863x; 1.0112x over previous
#include <cuda_runtime.h>
#include <math.h>

#define BSZ 32
#define CSZ 256
#define HH  56
#define WFQ 32
#define WWK 62
#define NPIX 3136
#define MSZ 16
#define KSZ 8
#define HIDN 16
#define PI_D 3.141592653589793238462643383279502884

typedef unsigned long long ull;

__device__ __forceinline__ ull d_fma2(ull a, ull b, ull c) {
    ull d;
    asm("fma.rn.f32x2 %0, %1, %2, %3;" : "=l"(d) : "l"(a), "l"(b), "l"(c));
    return d;
}
__device__ __forceinline__ ull d_dup(float x) {
    ull r;
    asm("mov.b64 %0, {%1, %1};" : "=l"(r) : "f"(x));
    return r;
}
__device__ __forceinline__ float2 d_unpack(ull v) {
    float2 r;
    asm("mov.b64 {%0, %1}, %2;" : "=f"(r.x), "=f"(r.y) : "l"(v));
    return r;
}

__device__ float  g_ctx[BSZ * CSZ];
__device__ float  g_hact[BSZ * HIDN];
__device__ float  g_coeffs[BSZ * CSZ * MSZ * KSZ];
__device__ float  g_yspec[(size_t)BSZ * CSZ * NPIX];
__device__ float  g_yconv[(size_t)BSZ * CSZ * NPIX];
__device__ float  g_bnA[CSZ], g_bnB[CSZ];

__device__ float2 g_FwRT[HH * WFQ];   // [w0][v]
__device__ float2 g_Fh[HH * HH];      // [u][h]
__device__ float2 g_Gh[HH * HH];      // [h][u]
__device__ float2 g_GwT[WFQ * HH];    // [v][w0]

__device__ double g_Rf[WWK * HH];
__device__ double g_Rb[HH * WWK];
__device__ double g_tw62r[WWK], g_tw62i[WWK];

__device__ double rz_fwd(int j, int i) {           // 56 -> 62, ks = 1
    double s = (j + 0.5) * (56.0 / 62.0) - 0.5;
    double w = fmax(0.0, 1.0 - fabs(s - (double)i));
    double denom = 0.0;
    int i0 = (int)floor(s);
    for (int q = i0; q <= i0 + 1; ++q)
        if (q >= 0 && q < 56) denom += fmax(0.0, 1.0 - fabs(s - (double)q));
    return w / denom;
}
__device__ double rz_bwd(int j, int i) {           // 62 -> 56, antialias ks = 62/56
    double ks = 62.0 / 56.0;
    double s = (j + 0.5) * ks - 0.5;
    double w = fmax(0.0, 1.0 - fabs(s - (double)i) / ks);
    double denom = 0.0;
    int lo = (int)ceil(s - ks), hi = (int)floor(s + ks);
    if (lo < 0) lo = 0;
    if (hi > 61) hi = 61;
    for (int q = lo; q <= hi; ++q)
        denom += fmax(0.0, 1.0 - fabs(s - (double)q) / ks);
    return w / denom;
}

__global__ void k_init0() {
    int t = threadIdx.x;
    if (t < WWK) { double a = -2.0 * PI_D * t / 62.0; g_tw62r[t] = cos(a); g_tw62i[t] = sin(a); }
    for (int i = t; i < WWK * HH; i += blockDim.x) g_Rf[i] = rz_fwd(i / HH, i % HH);
    for (int i = t; i < HH * WWK; i += blockDim.x) g_Rb[i] = rz_bwd(i / WWK, i % WWK);
}

__global__ void k_init1() {
    const double SC = 1.0 / sqrt(56.0 * 62.0);
    int total = 1792 + 1792 + 3136 + 3136;
    for (int idx = blockIdx.x * blockDim.x + threadIdx.x; idx < total; idx += gridDim.x * blockDim.x) {
        if (idx < 1792) {                      // FwRT[w0][v]
            int w0 = idx / WFQ, v = idx % WFQ;
            double ar = 0, ai = 0;
            for (int w = 0; w < WWK; ++w) {
                double r = g_Rf[w * HH + w0]; int m = (v * w) % WWK;
                ar += g_tw62r[m] * r; ai += g_tw62i[m] * r;
            }
            g_FwRT[w0 * WFQ + v] = make_float2((float)(ar * SC), (float)(ai * SC));
        } else if (idx < 3584) {               // GwT[v][w0]
            int j = idx - 1792; int v = j / HH, w0 = j % HH;
            double cv = (v == 0 || v == 31) ? 1.0 : 2.0;
            double ar = 0, ai = 0;
            for (int w = 0; w < WWK; ++w) {
                double r = g_Rb[w0 * WWK + w]; int m = (v * w) % WWK;
                ar += g_tw62r[m] * r; ai -= g_tw62i[m] * r;
            }
            g_GwT[v * HH + w0] = make_float2((float)(ar * cv * SC), (float)(ai * cv * SC));
        } else if (idx < 6720) {               // Fh[u][h]
            int j = idx - 3584; int u = j / HH, h = j % HH;
            double a = -2.0 * PI_D * ((u * h) % HH) / 56.0;
            g_Fh[u * HH + h] = make_float2((float)cos(a), (float)sin(a));
        } else {                               // Gh[h][u]
            int j = idx - 6720; int h = j / HH, u = j % HH;
            double a = 2.0 * PI_D * ((u * h) % HH) / 56.0;
            g_Gh[h * HH + u] = make_float2((float)cos(a), (float)(sin(a)));
        }
    }
}

__global__ void k_ctx(const float* __restrict__ x) {
    int plane = blockIdx.x;
    const float4* p = (const float4*)(x + (size_t)plane * NPIX);
    float s = 0.f;
    for (int i = threadIdx.x; i < NPIX / 4; i += blockDim.x) {
        float4 v = p[i]; s += v.x + v.y + v.z + v.w;
    }
    for (int o = 16; o > 0; o >>= 1) s += __shfl_xor_sync(0xffffffffu, s, o);
    __shared__ float red[4];
    int warp = threadIdx.x >> 5, lane = threadIdx.x & 31;
    if (lane == 0) red[warp] = s;
    __syncthreads();
    if (threadIdx.x == 0)
        g_ctx[plane] = (red[0] + red[1] + red[2] + red[3]) * (1.0f / NPIX);
}

__global__ void __launch_bounds__(256) k_head1(
    const float* __restrict__ fc1_w, const float* __restrict__ fc1_b,
    const float* __restrict__ ln_g,  const float* __restrict__ ln_b)
{
    int b = blockIdx.x, t = threadIdx.x;
    int warp = t >> 5, lane = t & 31;
    __shared__ float sctx[CSZ];
    __shared__ float shid[HIDN];
    __shared__ float sstat[2];
    sctx[t] = g_ctx[b * CSZ + t];
    __syncthreads();
    for (int rep = 0; rep < 2; ++rep) {
        int hidx = warp * 2 + rep;
        float acc = 0.f;
        for (int c = lane; c < CSZ; c += 32) acc += sctx[c] * fc1_w[hidx * CSZ + c];
        for (int o = 16; o > 0; o >>= 1) acc += __shfl_xor_sync(0xffffffffu, acc, o);
        if (lane == 0) shid[hidx] = acc + fc1_b[hidx];
    }
    __syncthreads();
    if (t == 0) {
        float mu = 0.f;
        for (int i = 0; i < HIDN; ++i) mu += shid[i];
        mu *= (1.0f / HIDN);
        float var = 0.f;
        for (int i = 0; i < HIDN; ++i) { float d = shid[i] - mu; var += d * d; }
        sstat[0] = mu; sstat[1] = rsqrtf(var * (1.0f / HIDN) + 1e-5f);
    }
    __syncthreads();
    if (t < HIDN)
        g_hact[b * HIDN + t] =
            fmaxf((shid[t] - sstat[0]) * sstat[1] * ln_g[t] + ln_b[t], 0.f);
}

__global__ void __launch_bounds__(256) k_head2(
    const float* __restrict__ fh_w, const float* __restrict__ fh_b)
{
    __shared__ float sH[BSZ * 17];
    int t = threadIdx.x;
    for (int i = t; i < BSZ * HIDN; i += 256)
        sH[(i >> 4) * 17 + (i & 15)] = g_hact[i];
    __syncthreads();
    int b = t & 31;
    int grp = blockIdx.x * 8 + (t >> 5);
    float h[HIDN];
#pragma unroll
    for (int i = 0; i < HIDN; ++i) h[i] = sH[b * 17 + i];

    const float4* wp = (const float4*)(fh_w + (size_t)grp * KSZ * HIDN);
    float lg[KSZ]; float mx = -1e30f;
#pragma unroll
    for (int k = 0; k < KSZ; ++k) {
        float4 w0 = wp[k * 4 + 0], w1 = wp[k * 4 + 1], w2 = wp[k * 4 + 2], w3 = wp[k * 4 + 3];
        float a = fh_b[grp * KSZ + k];
        a += h[0]*w0.x + h[1]*w0.y + h[2]*w0.z + h[3]*w0.w;
        a += h[4]*w1.x + h[5]*w1.y + h[6]*w1.z + h[7]*w1.w;
        a += h[8]*w2.x + h[9]*w2.y + h[10]*w2.z + h[11]*w2.w;
        a += h[12]*w3.x + h[13]*w3.y + h[14]*w3.z + h[15]*w3.w;
        lg[k] = a; mx = fmaxf(mx, a);
    }
    float sum = 0.f;
#pragma unroll
    for (int k = 0; k < KSZ; ++k) { lg[k] = expf(lg[k] - mx); sum += lg[k]; }
    float inv = 1.0f / sum;
    float* out = g_coeffs + (size_t)b * (CSZ * MSZ * KSZ) + grp * KSZ;
    ((float4*)out)[0] = make_float4(lg[0]*inv, lg[1]*inv, lg[2]*inv, lg[3]*inv);
    ((float4*)out)[1] = make_float4(lg[4]*inv, lg[5]*inv, lg[6]*inv, lg[7]*inv);
}

// per-plane fused resize/DFT/mask/iDFT/resize (f32x2 packed row-pair mainloops)
__global__ void __launch_bounds__(256) k_spec(
    const float* __restrict__ x,
    const float* __restrict__ br, const float* __restrict__ bi)
{
    __shared__ __align__(16) float sm[10432];
    float2* B1 = (float2*)sm;                  // 1792 f2
    float2* B2 = (float2*)(sm + 3584);         // 1792 f2
    float*  BX = sm + 7168;                    // 3136 f (aliased by Bq)
    float4* Bq = (float4*)(sm + 7168);         // 14*56 float4 = 3136 f
    float*  sCo = sm + 10304;                  // 128 f

    int plane = blockIdx.x;
    int t = threadIdx.x, warp = t >> 5, lane = t & 31;
    const float* xp = x + (size_t)plane * NPIX;

    for (int i = t; i < NPIX; i += 256) BX[i] = xp[i];
    if (t < 128) sCo[t] = g_coeffs[(size_t)plane * 128 + t];
    for (int i = t; i < 1792; i += 256) B1[i] = g_FwRT[i];
    __syncthreads();

    // S2: T1[h][v] = sum_w x[h][w] * FwRT[w][v]  -> B2
    {
        float2 acc[7];
#pragma unroll
        for (int r = 0; r < 7; ++r) acc[r] = make_float2(0.f, 0.f);
        int h0 = warp * 7;
        for (int w = 0; w < HH; w += 2) {
            float2 f0 = B1[w * WFQ + lane];
            float2 f1 = B1[(w + 1) * WFQ + lane];
#pragma unroll
            for (int r = 0; r < 7; ++r) {
                float2 a = *(const float2*)&BX[(h0 + r) * HH + w];
                acc[r].x += a.x * f0.x + a.y * f1.x;
                acc[r].y += a.x * f0.y + a.y * f1.y;
            }
        }
#pragma unroll
        for (int r = 0; r < 7; ++r) B2[(h0 + r) * WFQ + lane] = acc[r];
    }
    __syncthreads();

    // S3: X = Fh @ T1 (row-pair packed), mask -> Y in B1. Fh streamed in halves of 28 rows (14 pairs).
    for (int half = 0; half < 2; ++half) {
        int ub = half * 28;
        // Bq[p*56+h] = (Fh[ub+2p][h].re, Fh[ub+2p+1][h].re, Fh[ub+2p][h].im, Fh[ub+2p+1][h].im)
        for (int i = t; i < 14 * HH; i += 256) {
            int p = i / HH, h = i % HH;
            float2 f0 = g_Fh[(ub + 2 * p) * HH + h];
            float2 f1 = g_Fh[(ub + 2 * p + 1) * HH + h];
            Bq[i] = make_float4(f0.x, f1.x, f0.y, f1.y);
        }
        __syncthreads();
        ull ar[2] = {0, 0}, ai[2] = {0, 0};     // (row0,row1) per pair
        int p1ok = (warp + 8) < 14;
        for (int h = 0; h < HH; ++h) {
            float2 tt = B2[h * WFQ + lane];
            ull ttx = d_dup(tt.x), tty = d_dup(tt.y), ttyn = d_dup(-tt.y);
            float4 q0 = Bq[warp * HH + h];
            ull fx0 = *(ull*)&q0.x, fy0 = *(ull*)&q0.z;
            ar[0] = d_fma2(fx0, ttx, ar[0]); ar[0] = d_fma2(fy0, ttyn, ar[0]);
            ai[0] = d_fma2(fy0, ttx, ai[0]); ai[0] = d_fma2(fx0, tty, ai[0]);
            if (p1ok) {
                float4 q1 = Bq[(warp + 8) * HH + h];
                ull fx1 = *(ull*)&q1.x, fy1 = *(ull*)&q1.z;
                ar[1] = d_fma2(fx1, ttx, ar[1]); ar[1] = d_fma2(fy1, ttyn, ar[1]);
                ai[1] = d_fma2(fy1, ttx, ai[1]); ai[1] = d_fma2(fx1, tty, ai[1]);
            }
        }
#pragma unroll
        for (int pp = 0; pp < 2; ++pp) {
            int p = warp + 8 * pp;
            if (p < 14) {
                float2 re = d_unpack(ar[pp]), im = d_unpack(ai[pp]);
#pragma unroll
                for (int j = 0; j < 2; ++j) {
                    int u = ub + 2 * p + j;
                    const float* co = sCo + ((u / 14) * 4 + (lane >> 3)) * KSZ;
                    float mr = 0.f, mi = 0.f;
#pragma unroll
                    for (int k = 0; k < KSZ; ++k) {
                        int bidx = k * (HH * WFQ) + u * WFQ + lane;
                        mr += co[k] * br[bidx];
                        mi += co[k] * bi[bidx];
                    }
                    float xr = j ? re.y : re.x, xi = j ? im.y : im.x;
                    B1[u * WFQ + lane] = make_float2(xr * mr - xi * mi, xr * mi + xi * mr);
                }
            }
        }
        __syncthreads();
    }

    // S4: T2 = Gh @ Y (row-pair packed) -> B2
    for (int half = 0; half < 2; ++half) {
        int hb = half * 28;
        for (int i = t; i < 14 * HH; i += 256) {
            int p = i / HH, u = i % HH;
            float2 f0 = g_Gh[(hb + 2 * p) * HH + u];
            float2 f1 = g_Gh[(hb + 2 * p + 1) * HH + u];
            Bq[i] = make_float4(f0.x, f1.x, f0.y, f1.y);
        }
        __syncthreads();
        ull ar[2] = {0, 0}, ai[2] = {0, 0};
        int p1ok = (warp + 8) < 14;
        for (int u = 0; u < HH; ++u) {
            float2 yy = B1[u * WFQ + lane];
            ull yx = d_dup(yy.x), yyp = d_dup(yy.y), yyn = d_dup(-yy.y);
            float4 q0 = Bq[warp * HH + u];
            ull fx0 = *(ull*)&q0.x, fy0 = *(ull*)&q0.z;
            ar[0] = d_fma2(fx0, yx, ar[0]); ar[0] = d_fma2(fy0, yyn, ar[0]);
            ai[0] = d_fma2(fy0, yx, ai[0]); ai[0] = d_fma2(fx0, yyp, ai[0]);
            if (p1ok) {
                float4 q1 = Bq[(warp + 8) * HH + u];
                ull fx1 = *(ull*)&q1.x, fy1 = *(ull*)&q1.z;
                ar[1] = d_fma2(fx1, yx, ar[1]); ar[1] = d_fma2(fy1, yyn, ar[1]);
                ai[1] = d_fma2(fy1, yx, ai[1]); ai[1] = d_fma2(fx1, yyp, ai[1]);
            }
        }
#pragma unroll
        for (int pp = 0; pp < 2; ++pp) {
            int p = warp + 8 * pp;
            if (p < 14) {
                float2 re = d_unpack(ar[pp]), im = d_unpack(ai[pp]);
                B2[(hb + 2 * p + 0) * WFQ + lane] = make_float2(re.x, im.x);
                B2[(hb + 2 * p + 1) * WFQ + lane] = make_float2(re.y, im.y);
            }
        }
        __syncthreads();
    }

    // S5: y[h][w0] = Re( T2[h][:] . GwT[:][w0] )
    for (int i = t; i < 1792; i += 256) B1[i] = g_GwT[i];
    __syncthreads();
    float* outp = g_yspec + (size_t)plane * NPIX;
    for (int grp = 0; grp < 2; ++grp) {
        int nr = grp ? 3 : 4;
        float a1[4] = {0.f, 0.f, 0.f, 0.f};
        float a2[4] = {0.f, 0.f, 0.f, 0.f};
        for (int v = 0; v < WFQ; ++v) {
            float2 g1 = B1[v * HH + lane];
            float2 g2 = (lane < 24) ? B1[v * HH + 32 + lane] : make_float2(0.f, 0.f);
#pragma unroll
            for (int r = 0; r < 4; ++r) {
                if (r < nr) {
                    float2 tt = B2[(warp + 8 * (grp * 4 + r)) * WFQ + v];
                    a1[r] += tt.x * g1.x - tt.y * g1.y;
                    a2[r] += tt.x * g2.x - tt.y * g2.y;
                }
            }
        }
#pragma unroll
        for (int r = 0; r < 4; ++r) {
            if (r < nr) {
                int h = warp + 8 * (grp * 4 + r);
                outp[h * HH + lane] = a1[r];
                if (lane < 24) outp[h * HH + 32 + lane] = a2[r];
            }
        }
    }
}

// 1x1 conv: 128x64 tile, 8 rows x 2 col-pairs per thread, f32x2 mainloop
__global__ void __launch_bounds__(256) k_conv(const float* __restrict__ W) {
    __shared__ float2 Asd[16][128];   // duplicated (a,a), 16KB
    __shared__ float  Bs[16][68];
    int b = blockIdx.z, mo = blockIdx.y * 128, no = blockIdx.x * 64;
    const float* Y = g_yspec + (size_t)b * CSZ * NPIX;
    float* Out = g_yconv + (size_t)b * CSZ * NPIX;
    int t = threadIdx.x;
    int tx = t & 15, ty = t >> 4;
    ull acc[8][2] = {};
    for (int kk = 0; kk < CSZ; kk += 16) {
#pragma unroll
        for (int it = 0; it < 2; ++it) {
            int r = (t >> 2) + 64 * it, q = t & 3;
            float4 wv = *(const float4*)&W[(size_t)(mo + r) * CSZ + kk + q * 4];
            Asd[q * 4 + 0][r] = make_float2(wv.x, wv.x);
            Asd[q * 4 + 1][r] = make_float2(wv.y, wv.y);
            Asd[q * 4 + 2][r] = make_float2(wv.z, wv.z);
            Asd[q * 4 + 3][r] = make_float2(wv.w, wv.w);
        }
        float4 yv = *(const float4*)&Y[(size_t)(kk + (t >> 4)) * NPIX + no + (t & 15) * 4];
        *(float4*)&Bs[t >> 4][(t & 15) * 4] = yv;
        __syncthreads();
#pragma unroll
        for (int k = 0; k < 16; ++k) {
            float4 bv = *(float4*)&Bs[k][tx * 4];
            ull pb0 = *(ull*)&bv.x, pb1 = *(ull*)&bv.z;
            ull a[8];
#pragma unroll
            for (int iq = 0; iq < 4; ++iq) {
                float4 av = *(float4*)&Asd[k][ty * 8 + iq * 2];
                a[iq * 2 + 0] = *(ull*)&av.x;
                a[iq * 2 + 1] = *(ull*)&av.z;
            }
#pragma unroll
            for (int i = 0; i < 8; ++i) {
                acc[i][0] = d_fma2(a[i], pb0, acc[i][0]);
                acc[i][1] = d_fma2(a[i], pb1, acc[i][1]);
            }
        }
        __syncthreads();
    }
#pragma unroll
    for (int i = 0; i < 8; ++i) {
        float2 lo = d_unpack(acc[i][0]), hi = d_unpack(acc[i][1]);
        *(float4*)&Out[(size_t)(mo + ty * 8 + i) * NPIX + no + tx * 4] =
            make_float4(lo.x, lo.y, hi.x, hi.y);
    }
}

__global__ void k_bnstat(const float* __restrict__ bn_g, const float* __restrict__ bn_b) {
    int o = blockIdx.x, t = threadIdx.x;
    float s1 = 0.f, s2 = 0.f;
    for (int b = 0; b < BSZ; ++b) {
        const float* p = g_yconv + (size_t)b * CSZ * NPIX + (size_t)o * NPIX;
        for (int i = t; i < NPIX; i += 256) { float v = p[i]; s1 += v; s2 += v * v; }
    }
    __shared__ double r1[256], r2[256];
    r1[t] = s1; r2[t] = s2; __syncthreads();
    for (int st = 128; st > 0; st >>= 1) {
        if (t < st) { r1[t] += r1[t + st]; r2[t] += r2[t + st]; }
        __syncthreads();
    }
    if (t == 0) {
        double N = (double)BSZ * NPIX;
        double mean = r1[0] / N, var = r2[0] / N - (r1[0] / N) * (r1[0] / N);
        float inv = (float)(1.0 / sqrt(var + 1e-5));
        float A = bn_g[o] * inv;
        g_bnA[o] = A;
        g_bnB[o] = bn_b[o] - (float)mean * A;
    }
}

__global__ void k_bnapply(float* __restrict__ out) {
    int i4 = blockIdx.x * blockDim.x + threadIdx.x;
    int c = (i4 / (NPIX / 4)) % CSZ;
    float A = g_bnA[c], Bv = g_bnB[c];
    float4 v = ((const float4*)g_yconv)[i4];
    v.x = v.x * A + Bv; v.y = v.y * A + Bv; v.z = v.z * A + Bv; v.w = v.w * A + Bv;
    ((float4*)out)[i4] = v;
}

extern "C" void kernel_launch(void* const* d_in, const int* in_sizes, int n_in,
                              void* d_out, int out_size) {
    const float* x      = (const float*)d_in[0];
    const float* fc1_w  = (const float*)d_in[1];
    const float* fc1_b  = (const float*)d_in[2];
    const float* ln_g   = (const float*)d_in[3];
    const float* ln_b   = (const float*)d_in[4];
    const float* fh_w   = (const float*)d_in[5];
    const float* fh_b   = (const float*)d_in[6];
    const float* br     = (const float*)d_in[7];
    const float* bi     = (const float*)d_in[8];
    const float* conv_w = (const float*)d_in[9];
    const float* bn_g   = (const float*)d_in[10];
    const float* bn_b   = (const float*)d_in[11];
    (void)in_sizes; (void)n_in; (void)out_size;

    k_init0<<<1, 256>>>();
    k_init1<<<40, 256>>>();
    k_ctx<<<BSZ * CSZ, 128>>>(x);
    k_head1<<<BSZ, 256>>>(fc1_w, fc1_b, ln_g, ln_b);
    k_head2<<<512, 256>>>(fh_w, fh_b);
    k_spec<<<BSZ * CSZ, 256>>>(x, br, bi);
    dim3 gc(49, 2, BSZ);
    k_conv<<<gc, 256>>>(conv_w);
    k_bnstat<<<CSZ, 256>>>(bn_g, bn_b);
    k_bnapply<<<(BSZ * CSZ * NPIX) / 1024, 256>>>((float*)d_out);
}

// round 7
// speedup vs baseline: 1.4560x; 1.1319x over previous
#include <cuda_runtime.h>
#include <cuda_bf16.h>
#include <stdint.h>
#include <math.h>

#define BSZ 32
#define CSZ 256
#define HH  56
#define WFQ 32
#define WWK 62
#define NPIX 3136
#define MSZ 16
#define KSZ 8
#define HIDN 16
#define PI_D 3.141592653589793238462643383279502884

typedef unsigned long long ull;

__device__ __forceinline__ ull d_fma2(ull a, ull b, ull c) {
    ull d;
    asm("fma.rn.f32x2 %0, %1, %2, %3;" : "=l"(d) : "l"(a), "l"(b), "l"(c));
    return d;
}
__device__ __forceinline__ ull d_dup(float x) {
    ull r;
    asm("mov.b64 %0, {%1, %1};" : "=l"(r) : "f"(x));
    return r;
}
__device__ __forceinline__ float2 d_unpack(ull v) {
    float2 r;
    asm("mov.b64 {%0, %1}, %2;" : "=f"(r.x), "=f"(r.y) : "l"(v));
    return r;
}
__device__ __forceinline__ void mma_bf16(float* d, const uint32_t* a, const uint32_t* b) {
    asm("mma.sync.aligned.m16n8k16.row.col.f32.bf16.bf16.f32 "
        "{%0,%1,%2,%3}, {%4,%5,%6,%7}, {%8,%9}, {%0,%1,%2,%3};"
        : "+f"(d[0]), "+f"(d[1]), "+f"(d[2]), "+f"(d[3])
        : "r"(a[0]), "r"(a[1]), "r"(a[2]), "r"(a[3]), "r"(b[0]), "r"(b[1]));
}

// ----------------------------- device scratch -------------------------------
__device__ float  g_ctx[BSZ * CSZ];
__device__ float  g_hact[BSZ * HIDN];
__device__ float  g_coeffs[BSZ * CSZ * MSZ * KSZ];
__device__ float  g_yspec[(size_t)BSZ * CSZ * NPIX];
__device__ float  g_yconv[(size_t)BSZ * CSZ * NPIX];
__device__ float  g_bnA[CSZ], g_bnB[CSZ];
__device__ __nv_bfloat16 g_whl[2][CSZ * CSZ];

__device__ float2 g_FwRT[HH * WFQ];
__device__ float2 g_Fh[HH * HH];
__device__ float2 g_Gh[HH * HH];
__device__ float2 g_GwT[WFQ * HH];

__device__ double g_Rf[WWK * HH];
__device__ double g_Rb[HH * WWK];
__device__ double g_tw62r[WWK], g_tw62i[WWK];

__device__ double rz_fwd(int j, int i) {
    double s = (j + 0.5) * (56.0 / 62.0) - 0.5;
    double w = fmax(0.0, 1.0 - fabs(s - (double)i));
    double denom = 0.0;
    int i0 = (int)floor(s);
    for (int q = i0; q <= i0 + 1; ++q)
        if (q >= 0 && q < 56) denom += fmax(0.0, 1.0 - fabs(s - (double)q));
    return w / denom;
}
__device__ double rz_bwd(int j, int i) {
    double ks = 62.0 / 56.0;
    double s = (j + 0.5) * ks - 0.5;
    double w = fmax(0.0, 1.0 - fabs(s - (double)i) / ks);
    double denom = 0.0;
    int lo = (int)ceil(s - ks), hi = (int)floor(s + ks);
    if (lo < 0) lo = 0;
    if (hi > 61) hi = 61;
    for (int q = lo; q <= hi; ++q)
        denom += fmax(0.0, 1.0 - fabs(s - (double)q) / ks);
    return w / denom;
}

__global__ void k_init0() {
    int t = threadIdx.x;
    if (t < WWK) { double a = -2.0 * PI_D * t / 62.0; g_tw62r[t] = cos(a); g_tw62i[t] = sin(a); }
    for (int i = t; i < WWK * HH; i += blockDim.x) g_Rf[i] = rz_fwd(i / HH, i % HH);
    for (int i = t; i < HH * WWK; i += blockDim.x) g_Rb[i] = rz_bwd(i / WWK, i % WWK);
}

__global__ void k_init1() {
    const double SC = 1.0 / sqrt(56.0 * 62.0);
    int total = 1792 + 1792 + 3136 + 3136;
    for (int idx = blockIdx.x * blockDim.x + threadIdx.x; idx < total; idx += gridDim.x * blockDim.x) {
        if (idx < 1792) {
            int w0 = idx / WFQ, v = idx % WFQ;
            double ar = 0, ai = 0;
            for (int w = 0; w < WWK; ++w) {
                double r = g_Rf[w * HH + w0]; int m = (v * w) % WWK;
                ar += g_tw62r[m] * r; ai += g_tw62i[m] * r;
            }
            g_FwRT[w0 * WFQ + v] = make_float2((float)(ar * SC), (float)(ai * SC));
        } else if (idx < 3584) {
            int j = idx - 1792; int v = j / HH, w0 = j % HH;
            double cv = (v == 0 || v == 31) ? 1.0 : 2.0;
            double ar = 0, ai = 0;
            for (int w = 0; w < WWK; ++w) {
                double r = g_Rb[w0 * WWK + w]; int m = (v * w) % WWK;
                ar += g_tw62r[m] * r; ai -= g_tw62i[m] * r;
            }
            g_GwT[v * HH + w0] = make_float2((float)(ar * cv * SC), (float)(ai * cv * SC));
        } else if (idx < 6720) {
            int j = idx - 3584; int u = j / HH, h = j % HH;
            double a = -2.0 * PI_D * ((u * h) % HH) / 56.0;
            g_Fh[u * HH + h] = make_float2((float)cos(a), (float)sin(a));
        } else {
            int j = idx - 6720; int h = j / HH, u = j % HH;
            double a = 2.0 * PI_D * ((u * h) % HH) / 56.0;
            g_Gh[h * HH + u] = make_float2((float)cos(a), (float)(sin(a)));
        }
    }
}

__global__ void k_ctx(const float* __restrict__ x) {
    int plane = blockIdx.x;
    const float4* p = (const float4*)(x + (size_t)plane * NPIX);
    float s = 0.f;
    for (int i = threadIdx.x; i < NPIX / 4; i += blockDim.x) {
        float4 v = p[i]; s += v.x + v.y + v.z + v.w;
    }
    for (int o = 16; o > 0; o >>= 1) s += __shfl_xor_sync(0xffffffffu, s, o);
    __shared__ float red[4];
    int warp = threadIdx.x >> 5, lane = threadIdx.x & 31;
    if (lane == 0) red[warp] = s;
    __syncthreads();
    if (threadIdx.x == 0)
        g_ctx[plane] = (red[0] + red[1] + red[2] + red[3]) * (1.0f / NPIX);
}

__global__ void __launch_bounds__(256) k_head1(
    const float* __restrict__ fc1_w, const float* __restrict__ fc1_b,
    const float* __restrict__ ln_g,  const float* __restrict__ ln_b)
{
    int b = blockIdx.x, t = threadIdx.x;
    int warp = t >> 5, lane = t & 31;
    __shared__ float sctx[CSZ];
    __shared__ float shid[HIDN];
    __shared__ float sstat[2];
    sctx[t] = g_ctx[b * CSZ + t];
    __syncthreads();
    for (int rep = 0; rep < 2; ++rep) {
        int hidx = warp * 2 + rep;
        float acc = 0.f;
        for (int c = lane; c < CSZ; c += 32) acc += sctx[c] * fc1_w[hidx * CSZ + c];
        for (int o = 16; o > 0; o >>= 1) acc += __shfl_xor_sync(0xffffffffu, acc, o);
        if (lane == 0) shid[hidx] = acc + fc1_b[hidx];
    }
    __syncthreads();
    if (t == 0) {
        float mu = 0.f;
        for (int i = 0; i < HIDN; ++i) mu += shid[i];
        mu *= (1.0f / HIDN);
        float var = 0.f;
        for (int i = 0; i < HIDN; ++i) { float d = shid[i] - mu; var += d * d; }
        sstat[0] = mu; sstat[1] = rsqrtf(var * (1.0f / HIDN) + 1e-5f);
    }
    __syncthreads();
    if (t < HIDN)
        g_hact[b * HIDN + t] =
            fmaxf((shid[t] - sstat[0]) * sstat[1] * ln_g[t] + ln_b[t], 0.f);
}

__global__ void __launch_bounds__(256) k_head2(
    const float* __restrict__ fh_w, const float* __restrict__ fh_b)
{
    __shared__ float sH[BSZ * 17];
    int t = threadIdx.x;
    for (int i = t; i < BSZ * HIDN; i += 256)
        sH[(i >> 4) * 17 + (i & 15)] = g_hact[i];
    __syncthreads();
    int b = t & 31;
    int grp = blockIdx.x * 8 + (t >> 5);
    float h[HIDN];
#pragma unroll
    for (int i = 0; i < HIDN; ++i) h[i] = sH[b * 17 + i];

    const float4* wp = (const float4*)(fh_w + (size_t)grp * KSZ * HIDN);
    float lg[KSZ]; float mx = -1e30f;
#pragma unroll
    for (int k = 0; k < KSZ; ++k) {
        float4 w0 = wp[k * 4 + 0], w1 = wp[k * 4 + 1], w2 = wp[k * 4 + 2], w3 = wp[k * 4 + 3];
        float a = fh_b[grp * KSZ + k];
        a += h[0]*w0.x + h[1]*w0.y + h[2]*w0.z + h[3]*w0.w;
        a += h[4]*w1.x + h[5]*w1.y + h[6]*w1.z + h[7]*w1.w;
        a += h[8]*w2.x + h[9]*w2.y + h[10]*w2.z + h[11]*w2.w;
        a += h[12]*w3.x + h[13]*w3.y + h[14]*w3.z + h[15]*w3.w;
        lg[k] = a; mx = fmaxf(mx, a);
    }
    float sum = 0.f;
#pragma unroll
    for (int k = 0; k < KSZ; ++k) { lg[k] = expf(lg[k] - mx); sum += lg[k]; }
    float inv = 1.0f / sum;
    float* out = g_coeffs + (size_t)b * (CSZ * MSZ * KSZ) + grp * KSZ;
    ((float4*)out)[0] = make_float4(lg[0]*inv, lg[1]*inv, lg[2]*inv, lg[3]*inv);
    ((float4*)out)[1] = make_float4(lg[4]*inv, lg[5]*inv, lg[6]*inv, lg[7]*inv);
}

// per-plane fused resize/DFT/mask/iDFT/resize (unchanged from R4 passing)
__global__ void __launch_bounds__(256) k_spec(
    const float* __restrict__ x,
    const float* __restrict__ br, const float* __restrict__ bi)
{
    __shared__ __align__(16) float sm[10432];
    float2* B1 = (float2*)sm;
    float2* B2 = (float2*)(sm + 3584);
    float*  BX = sm + 7168;
    float4* Bq = (float4*)(sm + 7168);
    float*  sCo = sm + 10304;

    int plane = blockIdx.x;
    int t = threadIdx.x, warp = t >> 5, lane = t & 31;
    const float* xp = x + (size_t)plane * NPIX;

    for (int i = t; i < NPIX; i += 256) BX[i] = xp[i];
    if (t < 128) sCo[t] = g_coeffs[(size_t)plane * 128 + t];
    for (int i = t; i < 1792; i += 256) B1[i] = g_FwRT[i];
    __syncthreads();

    {
        float2 acc[7];
#pragma unroll
        for (int r = 0; r < 7; ++r) acc[r] = make_float2(0.f, 0.f);
        int h0 = warp * 7;
        for (int w = 0; w < HH; w += 2) {
            float2 f0 = B1[w * WFQ + lane];
            float2 f1 = B1[(w + 1) * WFQ + lane];
#pragma unroll
            for (int r = 0; r < 7; ++r) {
                float2 a = *(const float2*)&BX[(h0 + r) * HH + w];
                acc[r].x += a.x * f0.x + a.y * f1.x;
                acc[r].y += a.x * f0.y + a.y * f1.y;
            }
        }
#pragma unroll
        for (int r = 0; r < 7; ++r) B2[(h0 + r) * WFQ + lane] = acc[r];
    }
    __syncthreads();

    for (int half = 0; half < 2; ++half) {
        int ub = half * 28;
        for (int i = t; i < 14 * HH; i += 256) {
            int p = i / HH, h = i % HH;
            float2 f0 = g_Fh[(ub + 2 * p) * HH + h];
            float2 f1 = g_Fh[(ub + 2 * p + 1) * HH + h];
            Bq[i] = make_float4(f0.x, f1.x, f0.y, f1.y);
        }
        __syncthreads();
        ull ar[2] = {0, 0}, ai[2] = {0, 0};
        int p1ok = (warp + 8) < 14;
        for (int h = 0; h < HH; ++h) {
            float2 tt = B2[h * WFQ + lane];
            ull ttx = d_dup(tt.x), tty = d_dup(tt.y), ttyn = d_dup(-tt.y);
            float4 q0 = Bq[warp * HH + h];
            ull fx0 = *(ull*)&q0.x, fy0 = *(ull*)&q0.z;
            ar[0] = d_fma2(fx0, ttx, ar[0]); ar[0] = d_fma2(fy0, ttyn, ar[0]);
            ai[0] = d_fma2(fy0, ttx, ai[0]); ai[0] = d_fma2(fx0, tty, ai[0]);
            if (p1ok) {
                float4 q1 = Bq[(warp + 8) * HH + h];
                ull fx1 = *(ull*)&q1.x, fy1 = *(ull*)&q1.z;
                ar[1] = d_fma2(fx1, ttx, ar[1]); ar[1] = d_fma2(fy1, ttyn, ar[1]);
                ai[1] = d_fma2(fy1, ttx, ai[1]); ai[1] = d_fma2(fx1, tty, ai[1]);
            }
        }
#pragma unroll
        for (int pp = 0; pp < 2; ++pp) {
            int p = warp + 8 * pp;
            if (p < 14) {
                float2 re = d_unpack(ar[pp]), im = d_unpack(ai[pp]);
#pragma unroll
                for (int j = 0; j < 2; ++j) {
                    int u = ub + 2 * p + j;
                    const float* co = sCo + ((u / 14) * 4 + (lane >> 3)) * KSZ;
                    float mr = 0.f, mi = 0.f;
#pragma unroll
                    for (int k = 0; k < KSZ; ++k) {
                        int bidx = k * (HH * WFQ) + u * WFQ + lane;
                        mr += co[k] * br[bidx];
                        mi += co[k] * bi[bidx];
                    }
                    float xr = j ? re.y : re.x, xi = j ? im.y : im.x;
                    B1[u * WFQ + lane] = make_float2(xr * mr - xi * mi, xr * mi + xi * mr);
                }
            }
        }
        __syncthreads();
    }

    for (int half = 0; half < 2; ++half) {
        int hb = half * 28;
        for (int i = t; i < 14 * HH; i += 256) {
            int p = i / HH, u = i % HH;
            float2 f0 = g_Gh[(hb + 2 * p) * HH + u];
            float2 f1 = g_Gh[(hb + 2 * p + 1) * HH + u];
            Bq[i] = make_float4(f0.x, f1.x, f0.y, f1.y);
        }
        __syncthreads();
        ull ar[2] = {0, 0}, ai[2] = {0, 0};
        int p1ok = (warp + 8) < 14;
        for (int u = 0; u < HH; ++u) {
            float2 yy = B1[u * WFQ + lane];
            ull yx = d_dup(yy.x), yyp = d_dup(yy.y), yyn = d_dup(-yy.y);
            float4 q0 = Bq[warp * HH + u];
            ull fx0 = *(ull*)&q0.x, fy0 = *(ull*)&q0.z;
            ar[0] = d_fma2(fx0, yx, ar[0]); ar[0] = d_fma2(fy0, yyn, ar[0]);
            ai[0] = d_fma2(fy0, yx, ai[0]); ai[0] = d_fma2(fx0, yyp, ai[0]);
            if (p1ok) {
                float4 q1 = Bq[(warp + 8) * HH + u];
                ull fx1 = *(ull*)&q1.x, fy1 = *(ull*)&q1.z;
                ar[1] = d_fma2(fx1, yx, ar[1]); ar[1] = d_fma2(fy1, yyn, ar[1]);
                ai[1] = d_fma2(fy1, yx, ai[1]); ai[1] = d_fma2(fx1, yyp, ai[1]);
            }
        }
#pragma unroll
        for (int pp = 0; pp < 2; ++pp) {
            int p = warp + 8 * pp;
            if (p < 14) {
                float2 re = d_unpack(ar[pp]), im = d_unpack(ai[pp]);
                B2[(hb + 2 * p + 0) * WFQ + lane] = make_float2(re.x, im.x);
                B2[(hb + 2 * p + 1) * WFQ + lane] = make_float2(re.y, im.y);
            }
        }
        __syncthreads();
    }

    for (int i = t; i < 1792; i += 256) B1[i] = g_GwT[i];
    __syncthreads();
    float* outp = g_yspec + (size_t)plane * NPIX;
    for (int grp = 0; grp < 2; ++grp) {
        int nr = grp ? 3 : 4;
        float a1[4] = {0.f, 0.f, 0.f, 0.f};
        float a2[4] = {0.f, 0.f, 0.f, 0.f};
        for (int v = 0; v < WFQ; ++v) {
            float2 g1 = B1[v * HH + lane];
            float2 g2 = (lane < 24) ? B1[v * HH + 32 + lane] : make_float2(0.f, 0.f);
#pragma unroll
            for (int r = 0; r < 4; ++r) {
                if (r < nr) {
                    float2 tt = B2[(warp + 8 * (grp * 4 + r)) * WFQ + v];
                    a1[r] += tt.x * g1.x - tt.y * g1.y;
                    a2[r] += tt.x * g2.x - tt.y * g2.y;
                }
            }
        }
#pragma unroll
        for (int r = 0; r < 4; ++r) {
            if (r < nr) {
                int h = warp + 8 * (grp * 4 + r);
                outp[h * HH + lane] = a1[r];
                if (lane < 24) outp[h * HH + 32 + lane] = a2[r];
            }
        }
    }
}

// W -> bf16 hi/lo split
__global__ void k_wsplit(const float* __restrict__ W) {
    int i = blockIdx.x * blockDim.x + threadIdx.x;
    float v = W[i];
    __nv_bfloat16 hi = __float2bfloat16(v);
    __nv_bfloat16 lo = __float2bfloat16(v - __bfloat162float(hi));
    g_whl[0][i] = hi;
    g_whl[1][i] = lo;
}

// ---------------- 1x1 conv via mma.sync bf16 split precision ----------------
// Out[b][o][p] = sum_c W[o][c] Y[b][c][p]; acc += Whi*Yhi + Wlo*Yhi + Whi*Ylo
#define KC 32
#define ASTR 40   // smem row stride in bf16 elements (80B = 20 banks, conflict-free quads)
__global__ void __launch_bounds__(256) k_conv_mma() {
    __shared__ __nv_bfloat16 Ah[128 * ASTR];
    __shared__ __nv_bfloat16 Al[128 * ASTR];
    __shared__ __nv_bfloat16 Bh[128 * ASTR];
    __shared__ __nv_bfloat16 Bl[128 * ASTR];

    int t = threadIdx.x, wid = t >> 5, lane = t & 31;
    int p0 = blockIdx.x * 128;
    int mo = blockIdx.y * 128;
    int b  = blockIdx.z;
    const float* Y = g_yspec + (size_t)b * CSZ * NPIX;
    float* Out = g_yconv + (size_t)b * CSZ * NPIX;

    int wm = (wid & 1) * 64;       // warp tile 64 (m) x 32 (n)
    int wn = (wid >> 1) * 32;
    int qr = lane >> 2, qc = lane & 3;

    float acc[16][4];
#pragma unroll
    for (int i = 0; i < 16; ++i)
#pragma unroll
        for (int j = 0; j < 4; ++j) acc[i][j] = 0.f;

    for (int kk = 0; kk < CSZ; kk += KC) {
        // stage A: W hi/lo rows mo..mo+127, cols kk..kk+31 (m-major)
        {
            int r = t >> 1, cg = (t & 1) * 16;
            const __nv_bfloat16* w0 = &g_whl[0][(size_t)(mo + r) * CSZ + kk + cg];
            const __nv_bfloat16* w1 = &g_whl[1][(size_t)(mo + r) * CSZ + kk + cg];
            *(uint4*)&Ah[r * ASTR + cg]     = *(const uint4*)w0;
            *(uint4*)&Ah[r * ASTR + cg + 8] = *(const uint4*)(w0 + 8);
            *(uint4*)&Al[r * ASTR + cg]     = *(const uint4*)w1;
            *(uint4*)&Al[r * ASTR + cg + 8] = *(const uint4*)(w1 + 8);
        }
        // stage B: Y[kk+c][p0+..] floats -> Bh/Bl[n=p][k=c] (n-major, on-the-fly split)
        {
            int c = t >> 3, pg = (t & 7) * 16;
#pragma unroll
            for (int j = 0; j < 16; j += 4) {
                float4 v = make_float4(0.f, 0.f, 0.f, 0.f);
                if (p0 + pg + j < NPIX)
                    v = *(const float4*)&Y[(size_t)(kk + c) * NPIX + p0 + pg + j];
                float vv[4] = {v.x, v.y, v.z, v.w};
#pragma unroll
                for (int e = 0; e < 4; ++e) {
                    __nv_bfloat16 hi = __float2bfloat16(vv[e]);
                    __nv_bfloat16 lo = __float2bfloat16(vv[e] - __bfloat162float(hi));
                    Bh[(pg + j + e) * ASTR + c] = hi;
                    Bl[(pg + j + e) * ASTR + c] = lo;
                }
            }
        }
        __syncthreads();

#pragma unroll
        for (int ks = 0; ks < 2; ++ks) {
            int k0 = ks * 16;
            int cb = k0 + qc * 2;
            uint32_t afh[4][4], afl[4][4];
#pragma unroll
            for (int mf = 0; mf < 4; ++mf) {
                int r0 = wm + mf * 16 + qr;
                afh[mf][0] = *(uint32_t*)&Ah[r0 * ASTR + cb];
                afh[mf][1] = *(uint32_t*)&Ah[(r0 + 8) * ASTR + cb];
                afh[mf][2] = *(uint32_t*)&Ah[r0 * ASTR + cb + 8];
                afh[mf][3] = *(uint32_t*)&Ah[(r0 + 8) * ASTR + cb + 8];
                afl[mf][0] = *(uint32_t*)&Al[r0 * ASTR + cb];
                afl[mf][1] = *(uint32_t*)&Al[(r0 + 8) * ASTR + cb];
                afl[mf][2] = *(uint32_t*)&Al[r0 * ASTR + cb + 8];
                afl[mf][3] = *(uint32_t*)&Al[(r0 + 8) * ASTR + cb + 8];
            }
            uint32_t bf[4][2];
#pragma unroll
            for (int nf = 0; nf < 4; ++nf) {
                int n0 = wn + nf * 8 + qr;
                bf[nf][0] = *(uint32_t*)&Bh[n0 * ASTR + cb];
                bf[nf][1] = *(uint32_t*)&Bh[n0 * ASTR + cb + 8];
            }
#pragma unroll
            for (int mf = 0; mf < 4; ++mf)
#pragma unroll
                for (int nf = 0; nf < 4; ++nf) {
                    mma_bf16(acc[mf * 4 + nf], afh[mf], bf[nf]);   // Whi*Yhi
                    mma_bf16(acc[mf * 4 + nf], afl[mf], bf[nf]);   // Wlo*Yhi
                }
#pragma unroll
            for (int nf = 0; nf < 4; ++nf) {
                int n0 = wn + nf * 8 + qr;
                bf[nf][0] = *(uint32_t*)&Bl[n0 * ASTR + cb];
                bf[nf][1] = *(uint32_t*)&Bl[n0 * ASTR + cb + 8];
            }
#pragma unroll
            for (int mf = 0; mf < 4; ++mf)
#pragma unroll
                for (int nf = 0; nf < 4; ++nf)
                    mma_bf16(acc[mf * 4 + nf], afh[mf], bf[nf]);   // Whi*Ylo
        }
        __syncthreads();
    }

#pragma unroll
    for (int mf = 0; mf < 4; ++mf)
#pragma unroll
        for (int nf = 0; nf < 4; ++nf) {
            float* a = acc[mf * 4 + nf];
            int r = mo + wm + mf * 16 + qr;
            int cl = p0 + wn + nf * 8 + qc * 2;
            if (cl < NPIX) {
                *(float2*)&Out[(size_t)r * NPIX + cl] = make_float2(a[0], a[1]);
                *(float2*)&Out[(size_t)(r + 8) * NPIX + cl] = make_float2(a[2], a[3]);
            }
        }
}

__global__ void k_bnstat(const float* __restrict__ bn_g, const float* __restrict__ bn_b) {
    int o = blockIdx.x, t = threadIdx.x;
    float s1 = 0.f, s2 = 0.f;
    for (int b = 0; b < BSZ; ++b) {
        const float* p = g_yconv + (size_t)b * CSZ * NPIX + (size_t)o * NPIX;
        for (int i = t; i < NPIX; i += 256) { float v = p[i]; s1 += v; s2 += v * v; }
    }
    __shared__ double r1[256], r2[256];
    r1[t] = s1; r2[t] = s2; __syncthreads();
    for (int st = 128; st > 0; st >>= 1) {
        if (t < st) { r1[t] += r1[t + st]; r2[t] += r2[t + st]; }
        __syncthreads();
    }
    if (t == 0) {
        double N = (double)BSZ * NPIX;
        double mean = r1[0] / N, var = r2[0] / N - (r1[0] / N) * (r1[0] / N);
        float inv = (float)(1.0 / sqrt(var + 1e-5));
        float A = bn_g[o] * inv;
        g_bnA[o] = A;
        g_bnB[o] = bn_b[o] - (float)mean * A;
    }
}

__global__ void k_bnapply(float* __restrict__ out) {
    int i4 = blockIdx.x * blockDim.x + threadIdx.x;
    int c = (i4 / (NPIX / 4)) % CSZ;
    float A = g_bnA[c], Bv = g_bnB[c];
    float4 v = ((const float4*)g_yconv)[i4];
    v.x = v.x * A + Bv; v.y = v.y * A + Bv; v.z = v.z * A + Bv; v.w = v.w * A + Bv;
    ((float4*)out)[i4] = v;
}

extern "C" void kernel_launch(void* const* d_in, const int* in_sizes, int n_in,
                              void* d_out, int out_size) {
    const float* x      = (const float*)d_in[0];
    const float* fc1_w  = (const float*)d_in[1];
    const float* fc1_b  = (const float*)d_in[2];
    const float* ln_g   = (const float*)d_in[3];
    const float* ln_b   = (const float*)d_in[4];
    const float* fh_w   = (const float*)d_in[5];
    const float* fh_b   = (const float*)d_in[6];
    const float* br     = (const float*)d_in[7];
    const float* bi     = (const float*)d_in[8];
    const float* conv_w = (const float*)d_in[9];
    const float* bn_g   = (const float*)d_in[10];
    const float* bn_b   = (const float*)d_in[11];
    (void)in_sizes; (void)n_in; (void)out_size;

    k_init0<<<1, 256>>>();
    k_init1<<<40, 256>>>();
    k_ctx<<<BSZ * CSZ, 128>>>(x);
    k_head1<<<BSZ, 256>>>(fc1_w, fc1_b, ln_g, ln_b);
    k_head2<<<512, 256>>>(fh_w, fh_b);
    k_wsplit<<<256, 256>>>(conv_w);
    k_spec<<<BSZ * CSZ, 256>>>(x, br, bi);
    dim3 gc(25, 2, BSZ);
    k_conv_mma<<<gc, 256>>>();
    k_bnstat<<<CSZ, 256>>>(bn_g, bn_b);
    k_bnapply<<<(BSZ * CSZ * NPIX) / 1024, 256>>>((float*)d_out);
}